// round 13
// baseline (speedup 1.0000x reference)
#include <cuda_runtime.h>
#include <cstdint>
#include <math.h>

// Feature gate: tcgen05 PTX only assembles in the sm_103a (arch-specific) pass.
#if defined(__CUDA_ARCH__) && defined(__CUDA_ARCH_FEAT_SM103_ALL)
#define TC_OK 1
#else
#define TC_OK 0
#endif

// ---------------- problem constants ----------------
#define B_    64
#define A_    256
#define RD    512        // R == D
#define MEMN  4096
#define IN_   1024
#define HIDN  2048
#define NROW  (B_*A_)    // 16384
#define G3R   (3*RD)     // 1536

// ---------------- scratch ----------------
constexpr size_t OFF_QKV = 0;                                   // 16384*1536
constexpr size_t OFF_S    = OFF_QKV + (size_t)NROW*G3R;
constexpr size_t OFF_ST   = OFF_S   + (size_t)B_*A_*MEMN;
constexpr size_t OFF_MEMT = OFF_ST  + (size_t)B_*A_*MEMN;       // B*512*4096
constexpr size_t OFF_VT   = OFF_MEMT+ (size_t)B_*RD*MEMN;
constexpr size_t OFF_RD   = OFF_VT  + (size_t)B_*RD*A_;
constexpr size_t OFF_GX   = OFF_RD  + (size_t)NROW*RD;
constexpr size_t OFF_GIR  = OFF_GX  + (size_t)B_*G3R;
constexpr size_t OFF_GH   = OFF_GIR + (size_t)NROW*G3R;
constexpr size_t OFF_NPU  = OFF_GH  + (size_t)NROW*G3R;
constexpr size_t OFF_GATE = OFF_NPU + (size_t)NROW*IN_;
constexpr size_t OFF_TW   = OFF_GATE+ NROW;
constexpr size_t OFF_QP   = OFF_TW  + (size_t)B_*MEMN;
constexpr size_t OFF_ASC  = OFF_QP  + 1056;
constexpr size_t OFF_Y    = OFF_ASC + NROW;
constexpr size_t OFF_AGG  = OFF_Y   + (size_t)B_*IN_;
constexpr size_t SCR_TOTAL= OFF_AGG + (size_t)B_*HIDN;

__device__ float g_scr[SCR_TOTAL];

// ---------------- PTX helpers (guarded) ----------------
__device__ __forceinline__ uint32_t smem_u32(const void* p) {
    uint32_t a;
    asm("{ .reg .u64 t; cvta.to.shared.u64 t, %1; cvt.u32.u64 %0, t; }" : "=r"(a) : "l"(p));
    return a;
}

#if TC_OK
__device__ __forceinline__ uint32_t elect_one() {
    uint32_t p;
    asm volatile("{\n\t.reg .pred p;\n\telect.sync _|p, 0xFFFFFFFF;\n\tselp.b32 %0, 1, 0, p;\n\t}" : "=r"(p));
    return p;
}
__device__ __forceinline__ void mbar_init(uint32_t a, uint32_t cnt) {
    asm volatile("mbarrier.init.shared.b64 [%0], %1;" :: "r"(a), "r"(cnt) : "memory");
}
__device__ __forceinline__ void mbar_wait(uint32_t a, int phase) {
    asm volatile(
        "{\n\t.reg .pred P;\n\t"
        "WL%=:\n\t"
        "mbarrier.try_wait.parity.shared::cta.b64 P, [%0], %1, 0x989680;\n\t"
        "@!P bra WL%=;\n\t}"
        :: "r"(a), "r"(phase) : "memory");
}
__device__ __forceinline__ void tmem_alloc(uint32_t dst_smem, uint32_t ncols) {
    asm volatile("tcgen05.alloc.cta_group::1.sync.aligned.shared::cta.b32 [%0], %1;"
        :: "r"(dst_smem), "r"(ncols) : "memory");
}
__device__ __forceinline__ void tmem_dealloc(uint32_t tmem, uint32_t ncols) {
    asm volatile("tcgen05.dealloc.cta_group::1.sync.aligned.b32 %0, %1;" :: "r"(tmem), "r"(ncols));
}
__device__ __forceinline__ void tmem_relinquish() {
    asm volatile("tcgen05.relinquish_alloc_permit.cta_group::1.sync.aligned;");
}
__device__ __forceinline__ void tc_commit(uint32_t mbar) {
    asm volatile("tcgen05.commit.cta_group::1.mbarrier::arrive::one.shared::cluster.b64 [%0];"
        :: "r"(mbar) : "memory");
}
__device__ __forceinline__ void fence_async_shared() {
    asm volatile("fence.proxy.async.shared::cta;" ::: "memory");
}
__device__ __forceinline__ void tc_fence_after() {
    asm volatile("tcgen05.fence::after_thread_sync;" ::: "memory");
}
__device__ __forceinline__ void tc_wait_ld() {
    asm volatile("tcgen05.wait::ld.sync.aligned;" ::: "memory");
}
__device__ __forceinline__ void mma_tf32(uint32_t d, uint64_t ad, uint64_t bd, uint32_t idesc, uint32_t en) {
    asm volatile(
        "{\n\t.reg .pred p;\n\tsetp.ne.u32 p, %4, 0;\n\t"
        "tcgen05.mma.cta_group::1.kind::tf32 [%0], %1, %2, %3, {%5, %5, %5, %5}, p;\n\t}"
        :: "r"(d), "l"(ad), "l"(bd), "r"(idesc), "r"(en), "r"(0u) : "memory");
}
#define LDTM_X32(r, addr) \
    asm volatile("tcgen05.ld.sync.aligned.32x32b.x32.b32 " \
        "{%0,%1,%2,%3,%4,%5,%6,%7,%8,%9,%10,%11,%12,%13,%14,%15," \
        "%16,%17,%18,%19,%20,%21,%22,%23,%24,%25,%26,%27,%28,%29,%30,%31}, [%32];" \
        : "=r"((r)[0]),"=r"((r)[1]),"=r"((r)[2]),"=r"((r)[3]),"=r"((r)[4]),"=r"((r)[5]),"=r"((r)[6]),"=r"((r)[7]), \
          "=r"((r)[8]),"=r"((r)[9]),"=r"((r)[10]),"=r"((r)[11]),"=r"((r)[12]),"=r"((r)[13]),"=r"((r)[14]),"=r"((r)[15]), \
          "=r"((r)[16]),"=r"((r)[17]),"=r"((r)[18]),"=r"((r)[19]),"=r"((r)[20]),"=r"((r)[21]),"=r"((r)[22]),"=r"((r)[23]), \
          "=r"((r)[24]),"=r"((r)[25]),"=r"((r)[26]),"=r"((r)[27]),"=r"((r)[28]),"=r"((r)[29]),"=r"((r)[30]),"=r"((r)[31]) \
        : "r"(addr))

__device__ __forceinline__ uint32_t to_tf32(float x) {
    uint32_t r; asm("cvt.rna.tf32.f32 %0, %1;" : "=r"(r) : "f"(x)); return r;
}

// SW128 K-major descriptor: layout=2, version=1, SBO=64, LBO=1
static constexpr uint64_t DESC_BASE =
    (uint64_t(2) << 61) | (uint64_t(1) << 46) | (uint64_t(64) << 32) | (uint64_t(1) << 16);
__device__ __forceinline__ uint64_t mk_desc(uint32_t addr) {
    return DESC_BASE | ((uint64_t)(addr >> 4) & 0x3FFF);
}
// idesc: c=F32(1), a=TF32(2), b=TF32(2), N=128 (16<<17), M=128 (8<<24)
static constexpr uint32_t IDESC_TF32 = (1u<<4) | (2u<<7) | (2u<<10) | (16u<<17) | (8u<<24);
#endif  // TC_OK

// ---------------- GEMM (tensor 3xTF32 on sm_103a, fp32 fallback otherwise) ----
// C(M,N) = alpha * A(M,K) @ B(N,K)^T  [+ bias[n]]   (K-major both)
// EPI: C[m,n] = emem[m,n]*(1-clip(etw[m],0,1)) + alpha*acc
// M,N multiples of 128; K multiple of 32.
constexpr int TG_SMEM = 2*65536 + 1024;

template<bool EPI>
__global__ void __launch_bounds__(256, 1)
tgemm(int K, float alpha,
      const float* __restrict__ A, int lda, size_t sAz,
      const float* __restrict__ Bp, int ldb, size_t sBz,
      const float* __restrict__ bias,
      float* __restrict__ C, int ldc, size_t sCz,
      const float* __restrict__ emem, size_t sMem,
      const float* __restrict__ etw, int sTw)
{
    extern __shared__ char dsm_raw[];
    char* dsm = (char*)(((uintptr_t)dsm_raw + 1023) & ~(uintptr_t)1023);
    const int z = blockIdx.z;
    const float* Az = A  + (size_t)z*sAz + (size_t)blockIdx.x*128*lda;
    const float* Bz = Bp + (size_t)z*sBz + (size_t)blockIdx.y*128*ldb;
    const int tid = threadIdx.x;
    const int wid = tid >> 5, lid = tid & 31;

#if TC_OK
    // ================= tcgen05 3xTF32 path =================
    __shared__ uint32_t s_tmem[1];
    __shared__ uint64_t s_mbar[2];

    const uint32_t mbar0 = smem_u32(s_mbar);
    if (tid == 0) { mbar_init(mbar0, 1); mbar_init(mbar0 + 8, 1); }
    if (wid == 0) tmem_alloc(smem_u32(s_tmem), 128);
    __syncthreads();
    const uint32_t tmem = s_tmem[0];
    if (wid == 0) tmem_relinquish();

    const uint32_t dsm_u = smem_u32(dsm);
    const int NC = K >> 5;

    float4 pa[4], pb[4];
    #pragma unroll
    for (int it = 0; it < 4; it++) {
        int qa = it*256 + tid;
        int row = qa >> 3, kq = (qa & 7) * 4;
        pa[it] = *reinterpret_cast<const float4*>(Az + (size_t)row*lda + kq);
        pb[it] = *reinterpret_cast<const float4*>(Bz + (size_t)row*ldb + kq);
    }

    int par0 = 0, par1 = 0;
    for (int i = 0; i < NC; i++) {
        const int buf = i & 1;
        if (i >= 2) {
            if (buf == 0) { mbar_wait(mbar0, par0); par0 ^= 1; }
            else          { mbar_wait(mbar0 + 8, par1); par1 ^= 1; }
        }
        char* base = dsm + buf*65536;
        #pragma unroll
        for (int it = 0; it < 4; it++) {
            int qa = it*256 + tid;
            int row = qa >> 3;
            int off = row*128 + (qa & 7)*16;
            int sw = off ^ ((off >> 3) & 0x70);
            uint4 hi, lo;
            float4 v = pa[it];
            hi.x = to_tf32(v.x); lo.x = to_tf32(v.x - __uint_as_float(hi.x));
            hi.y = to_tf32(v.y); lo.y = to_tf32(v.y - __uint_as_float(hi.y));
            hi.z = to_tf32(v.z); lo.z = to_tf32(v.z - __uint_as_float(hi.z));
            hi.w = to_tf32(v.w); lo.w = to_tf32(v.w - __uint_as_float(hi.w));
            *reinterpret_cast<uint4*>(base + sw)         = hi;
            *reinterpret_cast<uint4*>(base + 16384 + sw) = lo;
            v = pb[it];
            hi.x = to_tf32(v.x); lo.x = to_tf32(v.x - __uint_as_float(hi.x));
            hi.y = to_tf32(v.y); lo.y = to_tf32(v.y - __uint_as_float(hi.y));
            hi.z = to_tf32(v.z); lo.z = to_tf32(v.z - __uint_as_float(hi.z));
            hi.w = to_tf32(v.w); lo.w = to_tf32(v.w - __uint_as_float(hi.w));
            *reinterpret_cast<uint4*>(base + 32768 + sw) = hi;
            *reinterpret_cast<uint4*>(base + 49152 + sw) = lo;
        }
        fence_async_shared();
        __syncthreads();

        if (wid == 0 && elect_one()) {
            uint32_t bu = dsm_u + buf*65536;
            uint64_t dAH = mk_desc(bu);
            uint64_t dAL = mk_desc(bu + 16384);
            uint64_t dBH = mk_desc(bu + 32768);
            uint64_t dBL = mk_desc(bu + 49152);
            #pragma unroll
            for (int ks = 0; ks < 4; ks++) {
                mma_tf32(tmem, dAH + 2*ks, dBH + 2*ks, IDESC_TF32, (i > 0 || ks > 0) ? 1u : 0u);
                mma_tf32(tmem, dAH + 2*ks, dBL + 2*ks, IDESC_TF32, 1u);
                mma_tf32(tmem, dAL + 2*ks, dBH + 2*ks, IDESC_TF32, 1u);
            }
            tc_commit(mbar0 + buf*8);
        }
        if (i + 1 < NC) {
            const float* ap = Az + (i + 1)*32;
            const float* bp = Bz + (i + 1)*32;
            #pragma unroll
            for (int it = 0; it < 4; it++) {
                int qa = it*256 + tid;
                int row = qa >> 3, kq = (qa & 7) * 4;
                pa[it] = *reinterpret_cast<const float4*>(ap + (size_t)row*lda + kq);
                pb[it] = *reinterpret_cast<const float4*>(bp + (size_t)row*ldb + kq);
            }
        }
    }
    {
        int lb = (NC - 1) & 1;
        if (lb == 0) mbar_wait(mbar0, par0);
        else         mbar_wait(mbar0 + 8, par1);
    }
    tc_fence_after();

    {
        const int wsub = wid & 3, wq = wid >> 2;
        const int m = blockIdx.x*128 + wsub*32 + lid;
        const int n0 = blockIdx.y*128;
        float keep = 1.f;
        const float* memrow = nullptr;
        if (EPI) {
            float t = etw[(size_t)z*sTw + m];
            t = fminf(fmaxf(t, 0.f), 1.f);
            keep = 1.f - t;
            memrow = emem + (size_t)z*sMem + (size_t)m*ldc;
        }
        float* crow = C + (size_t)z*sCz + (size_t)m*ldc;
        #pragma unroll
        for (int q = 0; q < 2; q++) {
            int nb = wq*2 + q;
            uint32_t r[32];
            LDTM_X32(r, tmem + nb*32);
            tc_wait_ld();
            int nb32 = n0 + nb*32;
            #pragma unroll
            for (int c = 0; c < 32; c += 4) {
                float4 o;
                o.x = alpha * __uint_as_float(r[c+0]);
                o.y = alpha * __uint_as_float(r[c+1]);
                o.z = alpha * __uint_as_float(r[c+2]);
                o.w = alpha * __uint_as_float(r[c+3]);
                if (EPI) {
                    float4 mm = *reinterpret_cast<const float4*>(memrow + nb32 + c);
                    o.x += mm.x * keep; o.y += mm.y * keep;
                    o.z += mm.z * keep; o.w += mm.w * keep;
                } else if (bias) {
                    o.x += bias[nb32 + c+0]; o.y += bias[nb32 + c+1];
                    o.z += bias[nb32 + c+2]; o.w += bias[nb32 + c+3];
                }
                *reinterpret_cast<float4*>(crow + nb32 + c) = o;
            }
        }
    }
    __syncthreads();
    if (wid == 0) tmem_dealloc(tmem, 128);

#else
    // ================= fp32 fallback path (non-sm_103a SASS) =================
    float (*As)[128] = reinterpret_cast<float(*)[128]>(dsm);
    float (*Bs)[128] = reinterpret_cast<float(*)[128]>(dsm + 8*128*sizeof(float));
    (void)lid;

    const int tx = tid & 15, ty = tid >> 4;
    float acc[8][8];
    #pragma unroll
    for (int i = 0; i < 8; i++)
        #pragma unroll
        for (int j = 0; j < 8; j++) acc[i][j] = 0.f;

    for (int k0 = 0; k0 < K; k0 += 8) {
        {
            int r = tid >> 1, kq = (tid & 1) * 4;
            float4 v = *reinterpret_cast<const float4*>(Az + (size_t)r * lda + (k0 + kq));
            As[kq + 0][r] = v.x; As[kq + 1][r] = v.y;
            As[kq + 2][r] = v.z; As[kq + 3][r] = v.w;
            float4 w = *reinterpret_cast<const float4*>(Bz + (size_t)r * ldb + (k0 + kq));
            Bs[kq + 0][r] = w.x; Bs[kq + 1][r] = w.y;
            Bs[kq + 2][r] = w.z; Bs[kq + 3][r] = w.w;
        }
        __syncthreads();
        #pragma unroll
        for (int k = 0; k < 8; k++) {
            float a[8], b[8];
            #pragma unroll
            for (int i = 0; i < 8; i++) a[i] = As[k][ty * 8 + i];
            #pragma unroll
            for (int j = 0; j < 8; j++) b[j] = Bs[k][tx * 8 + j];
            #pragma unroll
            for (int i = 0; i < 8; i++)
                #pragma unroll
                for (int j = 0; j < 8; j++)
                    acc[i][j] = fmaf(a[i], b[j], acc[i][j]);
        }
        __syncthreads();
    }
    #pragma unroll
    for (int i = 0; i < 8; i++) {
        int m = blockIdx.x*128 + ty * 8 + i;
        float t = 0.f;
        if (EPI) {
            t = etw[(size_t)z * sTw + m];
            t = fminf(fmaxf(t, 0.f), 1.f);
        }
        #pragma unroll
        for (int j = 0; j < 8; j++) {
            int n = blockIdx.y*128 + tx * 8 + j;
            float v = alpha * acc[i][j];
            if (EPI) {
                float mem = emem[(size_t)z * sMem + (size_t)m * ldc + n];
                C[(size_t)z*sCz + (size_t)m * ldc + n] = mem * (1.f - t) + v;
            } else {
                if (bias) v += bias[n];
                C[(size_t)z*sCz + (size_t)m * ldc + n] = v;
            }
        }
    }
#endif
}

// ---------------- transpose: dst[z][c][r] = src[z][r][c] ----------------
__global__ void transpose_k(const float* __restrict__ src, float* __restrict__ dst,
                            int lds, size_t sSrc, int ldd, size_t sDst)
{
    __shared__ float t[32][33];
    const int z = blockIdx.z;
    const int c0 = blockIdx.x * 32, r0 = blockIdx.y * 32;
    const float* s = src + (size_t)z * sSrc;
    float* d = dst + (size_t)z * sDst;
    const int tx = threadIdx.x, ty = threadIdx.y;
    #pragma unroll
    for (int i = 0; i < 32; i += 8)
        t[ty + i][tx] = s[(size_t)(r0 + ty + i) * lds + c0 + tx];
    __syncthreads();
    #pragma unroll
    for (int i = 0; i < 32; i += 8)
        d[(size_t)(c0 + ty + i) * ldd + r0 + tx] = t[tx][ty + i];
}

// ---------------- fp32 SGEMM (small GEMMs) ----------------
template<bool TA, bool TB, bool EPI>
__global__ __launch_bounds__(256, 2)
void gemm_k(int M, int N, int K, float alpha,
            const float* __restrict__ A, int lda, size_t sA,
            const float* __restrict__ Bp, int ldb, size_t sB,
            const float* __restrict__ bias,
            float* __restrict__ C, int ldc, size_t sC,
            const float* __restrict__ emem, size_t sMem,
            const float* __restrict__ etw, int sTw)
{
    const int bz = blockIdx.z;
    A  += (size_t)bz * sA;
    Bp += (size_t)bz * sB;
    C  += (size_t)bz * sC;
    const int m0 = blockIdx.x * 128;
    const int n0 = blockIdx.y * 128;

    __shared__ float As[8][128];
    __shared__ float Bs[8][128];

    const int tid = threadIdx.x;
    const int tx = tid & 15, ty = tid >> 4;

    float acc[8][8];
    #pragma unroll
    for (int i = 0; i < 8; i++)
        #pragma unroll
        for (int j = 0; j < 8; j++) acc[i][j] = 0.f;

    for (int k0 = 0; k0 < K; k0 += 8) {
        if (!TA) {
            int r = tid >> 1, kq = (tid & 1) * 4;
            int gm = m0 + r;
            float4 v = make_float4(0.f, 0.f, 0.f, 0.f);
            if (gm < M) v = *reinterpret_cast<const float4*>(A + (size_t)gm * lda + (k0 + kq));
            As[kq + 0][r] = v.x; As[kq + 1][r] = v.y;
            As[kq + 2][r] = v.z; As[kq + 3][r] = v.w;
        } else {
            int kr = tid >> 5, mq = (tid & 31) * 4;
            int gm = m0 + mq;
            float4 v = make_float4(0.f, 0.f, 0.f, 0.f);
            if (gm < M) v = *reinterpret_cast<const float4*>(A + (size_t)(k0 + kr) * lda + gm);
            *reinterpret_cast<float4*>(&As[kr][mq]) = v;
        }
        if (!TB) {
            int kr = tid >> 5, nq = (tid & 31) * 4;
            int gn = n0 + nq;
            float4 v = make_float4(0.f, 0.f, 0.f, 0.f);
            if (gn < N) v = *reinterpret_cast<const float4*>(Bp + (size_t)(k0 + kr) * ldb + gn);
            *reinterpret_cast<float4*>(&Bs[kr][nq]) = v;
        } else {
            int r = tid >> 1, kq = (tid & 1) * 4;
            int gn = n0 + r;
            float4 v = make_float4(0.f, 0.f, 0.f, 0.f);
            if (gn < N) v = *reinterpret_cast<const float4*>(Bp + (size_t)gn * ldb + (k0 + kq));
            Bs[kq + 0][r] = v.x; Bs[kq + 1][r] = v.y;
            Bs[kq + 2][r] = v.z; Bs[kq + 3][r] = v.w;
        }
        __syncthreads();
        #pragma unroll
        for (int k = 0; k < 8; k++) {
            float a[8], b[8];
            #pragma unroll
            for (int i = 0; i < 8; i++) a[i] = As[k][ty * 8 + i];
            #pragma unroll
            for (int j = 0; j < 8; j++) b[j] = Bs[k][tx * 8 + j];
            #pragma unroll
            for (int i = 0; i < 8; i++)
                #pragma unroll
                for (int j = 0; j < 8; j++)
                    acc[i][j] = fmaf(a[i], b[j], acc[i][j]);
        }
        __syncthreads();
    }
    #pragma unroll
    for (int i = 0; i < 8; i++) {
        int m = m0 + ty * 8 + i;
        if (m >= M) continue;
        float t = 0.f;
        if (EPI) {
            t = etw[(size_t)bz * sTw + m];
            t = fminf(fmaxf(t, 0.f), 1.f);
        }
        #pragma unroll
        for (int j = 0; j < 8; j++) {
            int n = n0 + tx * 8 + j;
            if (n >= N) continue;
            float v = alpha * acc[i][j];
            if (EPI) {
                float mem = emem[(size_t)bz * sMem + (size_t)m * ldc + n];
                C[(size_t)m * ldc + n] = mem * (1.f - t) + v;
            } else {
                if (bias) v += bias[n];
                C[(size_t)m * ldc + n] = v;
            }
        }
    }
}

// ---------------- small kernels ----------------
__device__ __forceinline__ float sigmoidf_(float x) { return 1.f / (1.f + __expf(-x)); }

__global__ void gate_dot(const float* __restrict__ H, const float* __restrict__ w,
                         const float* __restrict__ b, float* __restrict__ g)
{
    int gt = blockIdx.x * blockDim.x + threadIdx.x;
    int warp = gt >> 5, lane = gt & 31;
    if (warp >= NROW) return;
    const float* h = H + (size_t)warp * RD;
    float s = 0.f;
    for (int j = lane; j < RD; j += 32) s = fmaf(h[j], w[j], s);
    #pragma unroll
    for (int o = 16; o; o >>= 1) s += __shfl_xor_sync(0xffffffffu, s, o);
    if (lane == 0) g[warp] = sigmoidf_(s + b[0]);
}

__global__ void softmax4096(float* __restrict__ S, const float* __restrict__ gate)
{
    int row = blockIdx.x;
    float* p = S + (size_t)row * MEMN;
    __shared__ float buf[MEMN];
    __shared__ float red[256];
    int tid = threadIdx.x;
    float mx = -3.4e38f;
    for (int j = tid; j < MEMN; j += 256) { float v = p[j]; buf[j] = v; mx = fmaxf(mx, v); }
    red[tid] = mx; __syncthreads();
    for (int o = 128; o; o >>= 1) { if (tid < o) red[tid] = fmaxf(red[tid], red[tid + o]); __syncthreads(); }
    mx = red[0]; __syncthreads();
    float s = 0.f;
    for (int j = tid; j < MEMN; j += 256) { float e = __expf(buf[j] - mx); buf[j] = e; s += e; }
    red[tid] = s; __syncthreads();
    for (int o = 128; o; o >>= 1) { if (tid < o) red[tid] += red[tid + o]; __syncthreads(); }
    float inv = (gate ? gate[row] : 1.f) / red[0];
    for (int j = tid; j < MEMN; j += 256) p[j] = buf[j] * inv;
}

__global__ void tw_kernel(const float* __restrict__ S, float* __restrict__ tw)
{
    int m = blockIdx.x * blockDim.x + threadIdx.x;
    int b = blockIdx.y;
    const float* p = S + (size_t)b * A_ * MEMN + m;
    float s = 0.f;
    #pragma unroll 8
    for (int a = 0; a < A_; a++) s += p[(size_t)a * MEMN];
    tw[(size_t)b * MEMN + m] = s;
}

__global__ void gru_kernel(const float* __restrict__ gx, const float* __restrict__ gir,
                           const float* __restrict__ gh, const float* __restrict__ hidden,
                           float* __restrict__ nh)
{
    size_t t = (size_t)blockIdx.x * blockDim.x + threadIdx.x;
    if (t >= (size_t)NROW * RD) return;
    int row = (int)(t >> 9);
    int j   = (int)(t & 511);
    int b   = row >> 8;
    const float* gxr  = gx  + (size_t)b * G3R;
    const float* girr = gir + (size_t)row * G3R;
    const float* ghr  = gh  + (size_t)row * G3R;
    float r = sigmoidf_(gxr[j]        + girr[j]        + ghr[j]);
    float z = sigmoidf_(gxr[RD + j]   + girr[RD + j]   + ghr[RD + j]);
    float n = tanhf(gxr[2*RD + j] + girr[2*RD + j] + r * ghr[2*RD + j]);
    nh[t] = fmaf(z, hidden[t] - n, n);
}

__global__ void qp_kernel(const float* __restrict__ agg_q, const float* __restrict__ proj_w,
                          const float* __restrict__ proj_b, float* __restrict__ qp)
{
    if (blockIdx.x < 4) {
        int j = blockIdx.x * 256 + threadIdx.x;
        float s = 0.f;
        for (int h = 0; h < HIDN; h++) s = fmaf(agg_q[h], proj_w[(size_t)h * IN_ + j], s);
        qp[j] = s;
    } else {
        __shared__ float red[256];
        float s = 0.f;
        for (int h = threadIdx.x; h < HIDN; h += 256) s = fmaf(agg_q[h], proj_b[h], s);
        red[threadIdx.x] = s; __syncthreads();
        for (int o = 128; o; o >>= 1) { if (threadIdx.x < o) red[threadIdx.x] += red[threadIdx.x + o]; __syncthreads(); }
        if (threadIdx.x == 0) qp[IN_] = red[0];
    }
}

__global__ void aggscore_kernel(const float* __restrict__ npu, const float* __restrict__ qp,
                                float* __restrict__ sc)
{
    int gt = blockIdx.x * blockDim.x + threadIdx.x;
    int row = gt >> 5, lane = gt & 31;
    if (row >= NROW) return;
    const float* p = npu + (size_t)row * IN_;
    float s = 0.f;
    for (int j = lane; j < IN_; j += 32) s = fmaf(p[j], qp[j], s);
    #pragma unroll
    for (int o = 16; o; o >>= 1) s += __shfl_xor_sync(0xffffffffu, s, o);
    if (lane == 0) sc[row] = (s + qp[IN_]) * 0.022097086912079612f;
}

__global__ void aggsoftmax_kernel(float* __restrict__ sc)
{
    int b = blockIdx.x, tid = threadIdx.x;
    __shared__ float red[256];
    float v = sc[(size_t)b * A_ + tid];
    red[tid] = v; __syncthreads();
    for (int o = 128; o; o >>= 1) { if (tid < o) red[tid] = fmaxf(red[tid], red[tid + o]); __syncthreads(); }
    float mx = red[0]; __syncthreads();
    float e = __expf(v - mx);
    red[tid] = e; __syncthreads();
    for (int o = 128; o; o >>= 1) { if (tid < o) red[tid] += red[tid + o]; __syncthreads(); }
    sc[(size_t)b * A_ + tid] = e / red[0];
}

__global__ void y_kernel(const float* __restrict__ npu, const float* __restrict__ attn,
                         float* __restrict__ y)
{
    int j = blockIdx.x * blockDim.x + threadIdx.x;
    int b = blockIdx.y;
    const float* base = npu + (size_t)b * A_ * IN_ + j;
    float s = 0.f;
    for (int a = 0; a < A_; a++) s = fmaf(attn[(size_t)b * A_ + a], base[(size_t)a * IN_], s);
    y[(size_t)b * IN_ + j] = s;
}

__global__ void ln_kernel(const float* __restrict__ agg, const float* __restrict__ gamma,
                          const float* __restrict__ beta, float* __restrict__ out)
{
    int b = blockIdx.x, tid = threadIdx.x;
    __shared__ float r1[256], r2[256];
    const float* p = agg + (size_t)b * HIDN;
    float s = 0.f, ss = 0.f;
    for (int h = tid; h < HIDN; h += 256) { float v = p[h]; s += v; ss = fmaf(v, v, ss); }
    r1[tid] = s; r2[tid] = ss; __syncthreads();
    for (int o = 128; o; o >>= 1) {
        if (tid < o) { r1[tid] += r1[tid + o]; r2[tid] += r2[tid + o]; }
        __syncthreads();
    }
    float mu  = r1[0] * (1.f / HIDN);
    float var = r2[0] * (1.f / HIDN) - mu * mu;
    float inv = rsqrtf(var + 1e-5f);
    for (int h = tid; h < HIDN; h += 256)
        out[(size_t)b * HIDN + h] = (p[h] - mu) * inv * gamma[h] + beta[h];
}

// ---------------- host launch ----------------
extern "C" void kernel_launch(void* const* d_in, const int* in_sizes, int n_in,
                              void* d_out, int out_size)
{
    const float* x      = (const float*)d_in[0];
    const float* hidden = (const float*)d_in[1];
    const float* memory = (const float*)d_in[2];
    const float* mmu_w  = (const float*)d_in[3];
    const float* mmu_b  = (const float*)d_in[4];
    const float* w_ih   = (const float*)d_in[5];
    const float* b_ih   = (const float*)d_in[6];
    const float* w_hh   = (const float*)d_in[7];
    const float* b_hh   = (const float*)d_in[8];
    const float* out_w  = (const float*)d_in[9];
    const float* out_b  = (const float*)d_in[10];
    const float* agg_q  = (const float*)d_in[11];
    const float* proj_w = (const float*)d_in[12];
    const float* proj_b = (const float*)d_in[13];
    const float* gamma  = (const float*)d_in[14];
    const float* beta   = (const float*)d_in[15];

    float* out0    = (float*)d_out;
    float* hid_out = out0 + (size_t)B_ * HIDN;
    float* mem_out = hid_out + (size_t)NROW * RD;

    float* scr = nullptr;
    cudaGetSymbolAddress((void**)&scr, g_scr);
    float* qkv  = scr + OFF_QKV;
    float* S    = scr + OFF_S;
    float* St   = scr + OFF_ST;
    float* memT = scr + OFF_MEMT;
    float* Vt   = scr + OFF_VT;
    float* rd   = scr + OFF_RD;
    float* gx   = scr + OFF_GX;
    float* gir  = scr + OFF_GIR;
    float* gh   = scr + OFF_GH;
    float* npu  = scr + OFF_NPU;
    float* gate = scr + OFF_GATE;
    float* tw   = scr + OFF_TW;
    float* qp   = scr + OFF_QP;
    float* asc  = scr + OFF_ASC;
    float* y    = scr + OFF_Y;
    float* agg  = scr + OFF_AGG;

    cudaFuncSetAttribute(tgemm<false>, cudaFuncAttributeMaxDynamicSharedMemorySize, TG_SMEM);
    cudaFuncSetAttribute(tgemm<true>,  cudaFuncAttributeMaxDynamicSharedMemorySize, TG_SMEM);

    const float inv_d = 0.044194173824159216f;  // 1/sqrt(512)
    const dim3 tb(32, 8);

    // memT[z][d][m] = memory[z][m][d]
    transpose_k<<<dim3(RD/32, MEMN/32, B_), tb>>>(memory, memT, RD, (size_t)MEMN*RD, MEMN, (size_t)RD*MEMN);

    // QKV = hidden @ mmu_w[0:1536]^T + mmu_b
    tgemm<false><<<dim3(NROW/128, G3R/128, 1), 256, TG_SMEM>>>(RD, 1.f,
        hidden, RD, 0, mmu_w, RD, 0, mmu_b, qkv, G3R, 0, nullptr, 0, nullptr, 0);
    gate_dot<<<(NROW*32 + 255)/256, 256>>>(hidden, mmu_w + (size_t)3*RD*RD, mmu_b + 3*RD, gate);

    // read scores S = q @ memory^T * inv_d
    tgemm<false><<<dim3(A_/128, MEMN/128, B_), 256, TG_SMEM>>>(RD, inv_d,
        qkv, G3R, (size_t)A_*G3R, memory, RD, (size_t)MEMN*RD, nullptr,
        S, MEMN, (size_t)A_*MEMN, nullptr, 0, nullptr, 0);
    softmax4096<<<NROW, 256>>>(S, nullptr);
    // read_data = S @ memT^T
    tgemm<false><<<dim3(A_/128, RD/128, B_), 256, TG_SMEM>>>(MEMN, 1.f,
        S, MEMN, (size_t)A_*MEMN, memT, MEMN, (size_t)RD*MEMN, nullptr,
        rd, RD, (size_t)A_*RD, nullptr, 0, nullptr, 0);

    // write scores S = k @ memory^T * inv_d
    tgemm<false><<<dim3(A_/128, MEMN/128, B_), 256, TG_SMEM>>>(RD, inv_d,
        qkv + RD, G3R, (size_t)A_*G3R, memory, RD, (size_t)MEMN*RD, nullptr,
        S, MEMN, (size_t)A_*MEMN, nullptr, 0, nullptr, 0);
    softmax4096<<<NROW, 256>>>(S, gate);
    tw_kernel<<<dim3(MEMN/256, B_), 256>>>(S, tw);

    // St[z][m][a] = S[z][a][m];  Vt[z][d][a] = V[z][a][d]
    transpose_k<<<dim3(MEMN/32, A_/32, B_), tb>>>(S, St, MEMN, (size_t)A_*MEMN, A_, (size_t)MEMN*A_);
    transpose_k<<<dim3(RD/32, A_/32, B_), tb>>>(qkv + 2*RD, Vt, G3R, (size_t)A_*G3R, A_, (size_t)RD*A_);

    // new_memory = memory*(1-clip(tw)) + St @ Vt^T
    tgemm<true><<<dim3(MEMN/128, RD/128, B_), 256, TG_SMEM>>>(A_, 1.f,
        St, A_, (size_t)MEMN*A_, Vt, A_, (size_t)RD*A_, nullptr,
        mem_out, RD, (size_t)MEMN*RD, memory, (size_t)MEMN*RD, tw, MEMN);

    // GRU
    gemm_k<false,true,false><<<dim3(1,12,1), 256>>>(B_, G3R, IN_, 1.f,
        x, IN_, 0, w_ih, IN_ + RD, 0, b_ih, gx, G3R, 0, nullptr, 0, nullptr, 0);
    tgemm<false><<<dim3(NROW/128, G3R/128, 1), 256, TG_SMEM>>>(RD, 1.f,
        rd, RD, 0, w_ih + IN_, IN_ + RD, 0, nullptr, gir, G3R, 0, nullptr, 0, nullptr, 0);
    tgemm<false><<<dim3(NROW/128, G3R/128, 1), 256, TG_SMEM>>>(RD, 1.f,
        hidden, RD, 0, w_hh, RD, 0, b_hh, gh, G3R, 0, nullptr, 0, nullptr, 0);
    gru_kernel<<<((size_t)NROW*RD + 255)/256, 256>>>(gx, gir, gh, hidden, hid_out);

    // npu_out = new_regs @ out_w^T + out_b
    tgemm<false><<<dim3(NROW/128, IN_/128, 1), 256, TG_SMEM>>>(RD, 1.f,
        hid_out, RD, 0, out_w, RD, 0, out_b, npu, IN_, 0, nullptr, 0, nullptr, 0);

    // aggregation (proj GEMM eliminated by linearity)
    qp_kernel<<<5, 256>>>(agg_q, proj_w, proj_b, qp);
    aggscore_kernel<<<(NROW*32 + 255)/256, 256>>>(npu, qp, asc);
    aggsoftmax_kernel<<<B_, 256>>>(asc);
    y_kernel<<<dim3(IN_/256, B_), 256>>>(npu, asc, y);
    gemm_k<false,true,false><<<dim3(1,16,1), 256>>>(B_, HIDN, IN_, 1.f,
        y, IN_, 0, proj_w, IN_, 0, proj_b, agg, HIDN, 0, nullptr, 0, nullptr, 0);
    ln_kernel<<<B_, 256>>>(agg, gamma, beta, out0);
}

// round 14
// speedup vs baseline: 1.0113x; 1.0113x over previous
#include <cuda_runtime.h>
#include <cstdint>
#include <math.h>

// Feature gate: tcgen05 PTX only assembles in the sm_103a (arch-specific) pass.
#if defined(__CUDA_ARCH__) && defined(__CUDA_ARCH_FEAT_SM103_ALL)
#define TC_OK 1
#else
#define TC_OK 0
#endif

// ---------------- problem constants ----------------
#define B_    64
#define A_    256
#define RD    512        // R == D
#define MEMN  4096
#define IN_   1024
#define HIDN  2048
#define NROW  (B_*A_)    // 16384
#define G3R   (3*RD)     // 1536

// ---------------- scratch ----------------
constexpr size_t OFF_QKV = 0;                                   // 16384*1536
constexpr size_t OFF_S    = OFF_QKV + (size_t)NROW*G3R;
constexpr size_t OFF_ST   = OFF_S   + (size_t)B_*A_*MEMN;
constexpr size_t OFF_MEMT = OFF_ST  + (size_t)B_*A_*MEMN;       // B*512*4096
constexpr size_t OFF_VT   = OFF_MEMT+ (size_t)B_*RD*MEMN;
constexpr size_t OFF_RD   = OFF_VT  + (size_t)B_*RD*A_;
constexpr size_t OFF_GX   = OFF_RD  + (size_t)NROW*RD;
constexpr size_t OFF_GIR  = OFF_GX  + (size_t)B_*G3R;
constexpr size_t OFF_GH   = OFF_GIR + (size_t)NROW*G3R;
constexpr size_t OFF_NPU  = OFF_GH  + (size_t)NROW*G3R;
constexpr size_t OFF_GATE = OFF_NPU + (size_t)NROW*IN_;
constexpr size_t OFF_TW   = OFF_GATE+ NROW;
constexpr size_t OFF_QP   = OFF_TW  + (size_t)B_*MEMN;
constexpr size_t OFF_ASC  = OFF_QP  + 1056;
constexpr size_t OFF_Y    = OFF_ASC + NROW;
constexpr size_t OFF_AGG  = OFF_Y   + (size_t)B_*IN_;
constexpr size_t SCR_TOTAL= OFF_AGG + (size_t)B_*HIDN;

__device__ float g_scr[SCR_TOTAL];

// ---------------- PTX helpers (guarded) ----------------
__device__ __forceinline__ uint32_t smem_u32(const void* p) {
    uint32_t a;
    asm("{ .reg .u64 t; cvta.to.shared.u64 t, %1; cvt.u32.u64 %0, t; }" : "=r"(a) : "l"(p));
    return a;
}

#if TC_OK
__device__ __forceinline__ uint32_t elect_one() {
    uint32_t p;
    asm volatile("{\n\t.reg .pred p;\n\telect.sync _|p, 0xFFFFFFFF;\n\tselp.b32 %0, 1, 0, p;\n\t}" : "=r"(p));
    return p;
}
__device__ __forceinline__ void mbar_init(uint32_t a, uint32_t cnt) {
    asm volatile("mbarrier.init.shared.b64 [%0], %1;" :: "r"(a), "r"(cnt) : "memory");
}
__device__ __forceinline__ void mbar_wait(uint32_t a, int phase) {
    asm volatile(
        "{\n\t.reg .pred P;\n\t"
        "WL%=:\n\t"
        "mbarrier.try_wait.parity.shared::cta.b64 P, [%0], %1, 0x989680;\n\t"
        "@!P bra WL%=;\n\t}"
        :: "r"(a), "r"(phase) : "memory");
}
__device__ __forceinline__ void tmem_alloc(uint32_t dst_smem, uint32_t ncols) {
    asm volatile("tcgen05.alloc.cta_group::1.sync.aligned.shared::cta.b32 [%0], %1;"
        :: "r"(dst_smem), "r"(ncols) : "memory");
}
__device__ __forceinline__ void tmem_dealloc(uint32_t tmem, uint32_t ncols) {
    asm volatile("tcgen05.dealloc.cta_group::1.sync.aligned.b32 %0, %1;" :: "r"(tmem), "r"(ncols));
}
__device__ __forceinline__ void tmem_relinquish() {
    asm volatile("tcgen05.relinquish_alloc_permit.cta_group::1.sync.aligned;");
}
__device__ __forceinline__ void tc_commit(uint32_t mbar) {
    asm volatile("tcgen05.commit.cta_group::1.mbarrier::arrive::one.shared::cluster.b64 [%0];"
        :: "r"(mbar) : "memory");
}
__device__ __forceinline__ void fence_async_shared() {
    asm volatile("fence.proxy.async.shared::cta;" ::: "memory");
}
__device__ __forceinline__ void tc_fence_after() {
    asm volatile("tcgen05.fence::after_thread_sync;" ::: "memory");
}
__device__ __forceinline__ void tc_wait_ld() {
    asm volatile("tcgen05.wait::ld.sync.aligned;" ::: "memory");
}
__device__ __forceinline__ void mma_tf32(uint32_t d, uint64_t ad, uint64_t bd, uint32_t idesc, uint32_t en) {
    asm volatile(
        "{\n\t.reg .pred p;\n\tsetp.ne.u32 p, %4, 0;\n\t"
        "tcgen05.mma.cta_group::1.kind::tf32 [%0], %1, %2, %3, {%5, %5, %5, %5}, p;\n\t}"
        :: "r"(d), "l"(ad), "l"(bd), "r"(idesc), "r"(en), "r"(0u) : "memory");
}
#define LDTM_X32(r, addr) \
    asm volatile("tcgen05.ld.sync.aligned.32x32b.x32.b32 " \
        "{%0,%1,%2,%3,%4,%5,%6,%7,%8,%9,%10,%11,%12,%13,%14,%15," \
        "%16,%17,%18,%19,%20,%21,%22,%23,%24,%25,%26,%27,%28,%29,%30,%31}, [%32];" \
        : "=r"((r)[0]),"=r"((r)[1]),"=r"((r)[2]),"=r"((r)[3]),"=r"((r)[4]),"=r"((r)[5]),"=r"((r)[6]),"=r"((r)[7]), \
          "=r"((r)[8]),"=r"((r)[9]),"=r"((r)[10]),"=r"((r)[11]),"=r"((r)[12]),"=r"((r)[13]),"=r"((r)[14]),"=r"((r)[15]), \
          "=r"((r)[16]),"=r"((r)[17]),"=r"((r)[18]),"=r"((r)[19]),"=r"((r)[20]),"=r"((r)[21]),"=r"((r)[22]),"=r"((r)[23]), \
          "=r"((r)[24]),"=r"((r)[25]),"=r"((r)[26]),"=r"((r)[27]),"=r"((r)[28]),"=r"((r)[29]),"=r"((r)[30]),"=r"((r)[31]) \
        : "r"(addr))

__device__ __forceinline__ uint32_t to_tf32(float x) {
    uint32_t r; asm("cvt.rna.tf32.f32 %0, %1;" : "=r"(r) : "f"(x)); return r;
}

// SW128 K-major descriptor: layout=2, version=1, SBO=64, LBO=1
static constexpr uint64_t DESC_BASE =
    (uint64_t(2) << 61) | (uint64_t(1) << 46) | (uint64_t(64) << 32) | (uint64_t(1) << 16);
__device__ __forceinline__ uint64_t mk_desc(uint32_t addr) {
    return DESC_BASE | ((uint64_t)(addr >> 4) & 0x3FFF);
}
// idesc: c=F32(1), a=TF32(2), b=TF32(2), N=128 (16<<17), M=128 (8<<24)
static constexpr uint32_t IDESC_TF32 = (1u<<4) | (2u<<7) | (2u<<10) | (16u<<17) | (8u<<24);
#endif  // TC_OK

// ---------------- GEMM (tensor 3xTF32 on sm_103a, fp32 fallback otherwise) ----
// C(M,N) = alpha * A(M,K) @ B(N,K)^T  [+ bias[n]]   (K-major both)
// EPI: C[m,n] = emem[m,n]*(1-clip(etw[m],0,1)) + alpha*acc
// M,N multiples of 128; K multiple of 32.
constexpr int TG_SMEM = 2*65536 + 1024;

template<bool EPI>
__global__ void __launch_bounds__(256, 1)
tgemm(int K, float alpha,
      const float* __restrict__ A, int lda, size_t sAz,
      const float* __restrict__ Bp, int ldb, size_t sBz,
      const float* __restrict__ bias,
      float* __restrict__ C, int ldc, size_t sCz,
      const float* __restrict__ emem, size_t sMem,
      const float* __restrict__ etw, int sTw)
{
    extern __shared__ char dsm_raw[];
    char* dsm = (char*)(((uintptr_t)dsm_raw + 1023) & ~(uintptr_t)1023);
    const int z = blockIdx.z;
    const float* Az = A  + (size_t)z*sAz + (size_t)blockIdx.x*128*lda;
    const float* Bz = Bp + (size_t)z*sBz + (size_t)blockIdx.y*128*ldb;
    const int tid = threadIdx.x;
    const int wid = tid >> 5, lid = tid & 31;

#if TC_OK
    // ================= tcgen05 3xTF32 path =================
    __shared__ uint32_t s_tmem[1];
    __shared__ uint64_t s_mbar[2];

    const uint32_t mbar0 = smem_u32(s_mbar);
    if (tid == 0) { mbar_init(mbar0, 1); mbar_init(mbar0 + 8, 1); }
    if (wid == 0) tmem_alloc(smem_u32(s_tmem), 128);
    __syncthreads();
    const uint32_t tmem = s_tmem[0];
    if (wid == 0) tmem_relinquish();

    const uint32_t dsm_u = smem_u32(dsm);
    const int NC = K >> 5;

    float4 pa[4], pb[4];
    #pragma unroll
    for (int it = 0; it < 4; it++) {
        int qa = it*256 + tid;
        int row = qa >> 3, kq = (qa & 7) * 4;
        pa[it] = *reinterpret_cast<const float4*>(Az + (size_t)row*lda + kq);
        pb[it] = *reinterpret_cast<const float4*>(Bz + (size_t)row*ldb + kq);
    }

    int par0 = 0, par1 = 0;
    for (int i = 0; i < NC; i++) {
        const int buf = i & 1;
        if (i >= 2) {
            if (buf == 0) { mbar_wait(mbar0, par0); par0 ^= 1; }
            else          { mbar_wait(mbar0 + 8, par1); par1 ^= 1; }
        }
        char* base = dsm + buf*65536;
        #pragma unroll
        for (int it = 0; it < 4; it++) {
            int qa = it*256 + tid;
            int row = qa >> 3;
            int off = row*128 + (qa & 7)*16;
            int sw = off ^ ((off >> 3) & 0x70);
            uint4 hi, lo;
            float4 v = pa[it];
            hi.x = to_tf32(v.x); lo.x = to_tf32(v.x - __uint_as_float(hi.x));
            hi.y = to_tf32(v.y); lo.y = to_tf32(v.y - __uint_as_float(hi.y));
            hi.z = to_tf32(v.z); lo.z = to_tf32(v.z - __uint_as_float(hi.z));
            hi.w = to_tf32(v.w); lo.w = to_tf32(v.w - __uint_as_float(hi.w));
            *reinterpret_cast<uint4*>(base + sw)         = hi;
            *reinterpret_cast<uint4*>(base + 16384 + sw) = lo;
            v = pb[it];
            hi.x = to_tf32(v.x); lo.x = to_tf32(v.x - __uint_as_float(hi.x));
            hi.y = to_tf32(v.y); lo.y = to_tf32(v.y - __uint_as_float(hi.y));
            hi.z = to_tf32(v.z); lo.z = to_tf32(v.z - __uint_as_float(hi.z));
            hi.w = to_tf32(v.w); lo.w = to_tf32(v.w - __uint_as_float(hi.w));
            *reinterpret_cast<uint4*>(base + 32768 + sw) = hi;
            *reinterpret_cast<uint4*>(base + 49152 + sw) = lo;
        }
        fence_async_shared();
        __syncthreads();

        if (wid == 0 && elect_one()) {
            uint32_t bu = dsm_u + buf*65536;
            uint64_t dAH = mk_desc(bu);
            uint64_t dAL = mk_desc(bu + 16384);
            uint64_t dBH = mk_desc(bu + 32768);
            uint64_t dBL = mk_desc(bu + 49152);
            #pragma unroll
            for (int ks = 0; ks < 4; ks++) {
                mma_tf32(tmem, dAH + 2*ks, dBH + 2*ks, IDESC_TF32, (i > 0 || ks > 0) ? 1u : 0u);
                mma_tf32(tmem, dAH + 2*ks, dBL + 2*ks, IDESC_TF32, 1u);
                mma_tf32(tmem, dAL + 2*ks, dBH + 2*ks, IDESC_TF32, 1u);
            }
            tc_commit(mbar0 + buf*8);
        }
        if (i + 1 < NC) {
            const float* ap = Az + (i + 1)*32;
            const float* bp = Bz + (i + 1)*32;
            #pragma unroll
            for (int it = 0; it < 4; it++) {
                int qa = it*256 + tid;
                int row = qa >> 3, kq = (qa & 7) * 4;
                pa[it] = *reinterpret_cast<const float4*>(ap + (size_t)row*lda + kq);
                pb[it] = *reinterpret_cast<const float4*>(bp + (size_t)row*ldb + kq);
            }
        }
    }
    {
        int lb = (NC - 1) & 1;
        if (lb == 0) mbar_wait(mbar0, par0);
        else         mbar_wait(mbar0 + 8, par1);
    }
    tc_fence_after();

    {
        const int wsub = wid & 3, wq = wid >> 2;
        const int m = blockIdx.x*128 + wsub*32 + lid;
        const int n0 = blockIdx.y*128;
        float keep = 1.f;
        const float* memrow = nullptr;
        if (EPI) {
            float t = etw[(size_t)z*sTw + m];
            t = fminf(fmaxf(t, 0.f), 1.f);
            keep = 1.f - t;
            memrow = emem + (size_t)z*sMem + (size_t)m*ldc;
        }
        float* crow = C + (size_t)z*sCz + (size_t)m*ldc;
        #pragma unroll
        for (int q = 0; q < 2; q++) {
            int nb = wq*2 + q;
            uint32_t r[32];
            LDTM_X32(r, tmem + nb*32);
            tc_wait_ld();
            int nb32 = n0 + nb*32;
            #pragma unroll
            for (int c = 0; c < 32; c += 4) {
                float4 o;
                o.x = alpha * __uint_as_float(r[c+0]);
                o.y = alpha * __uint_as_float(r[c+1]);
                o.z = alpha * __uint_as_float(r[c+2]);
                o.w = alpha * __uint_as_float(r[c+3]);
                if (EPI) {
                    float4 mm = *reinterpret_cast<const float4*>(memrow + nb32 + c);
                    o.x += mm.x * keep; o.y += mm.y * keep;
                    o.z += mm.z * keep; o.w += mm.w * keep;
                } else if (bias) {
                    o.x += bias[nb32 + c+0]; o.y += bias[nb32 + c+1];
                    o.z += bias[nb32 + c+2]; o.w += bias[nb32 + c+3];
                }
                *reinterpret_cast<float4*>(crow + nb32 + c) = o;
            }
        }
    }
    __syncthreads();
    if (wid == 0) tmem_dealloc(tmem, 128);

#else
    // ================= fp32 fallback path (non-sm_103a SASS) =================
    float (*As)[128] = reinterpret_cast<float(*)[128]>(dsm);
    float (*Bs)[128] = reinterpret_cast<float(*)[128]>(dsm + 8*128*sizeof(float));
    (void)lid;

    const int tx = tid & 15, ty = tid >> 4;
    float acc[8][8];
    #pragma unroll
    for (int i = 0; i < 8; i++)
        #pragma unroll
        for (int j = 0; j < 8; j++) acc[i][j] = 0.f;

    for (int k0 = 0; k0 < K; k0 += 8) {
        {
            int r = tid >> 1, kq = (tid & 1) * 4;
            float4 v = *reinterpret_cast<const float4*>(Az + (size_t)r * lda + (k0 + kq));
            As[kq + 0][r] = v.x; As[kq + 1][r] = v.y;
            As[kq + 2][r] = v.z; As[kq + 3][r] = v.w;
            float4 w = *reinterpret_cast<const float4*>(Bz + (size_t)r * ldb + (k0 + kq));
            Bs[kq + 0][r] = w.x; Bs[kq + 1][r] = w.y;
            Bs[kq + 2][r] = w.z; Bs[kq + 3][r] = w.w;
        }
        __syncthreads();
        #pragma unroll
        for (int k = 0; k < 8; k++) {
            float a[8], b[8];
            #pragma unroll
            for (int i = 0; i < 8; i++) a[i] = As[k][ty * 8 + i];
            #pragma unroll
            for (int j = 0; j < 8; j++) b[j] = Bs[k][tx * 8 + j];
            #pragma unroll
            for (int i = 0; i < 8; i++)
                #pragma unroll
                for (int j = 0; j < 8; j++)
                    acc[i][j] = fmaf(a[i], b[j], acc[i][j]);
        }
        __syncthreads();
    }
    #pragma unroll
    for (int i = 0; i < 8; i++) {
        int m = blockIdx.x*128 + ty * 8 + i;
        float t = 0.f;
        if (EPI) {
            t = etw[(size_t)z * sTw + m];
            t = fminf(fmaxf(t, 0.f), 1.f);
        }
        #pragma unroll
        for (int j = 0; j < 8; j++) {
            int n = blockIdx.y*128 + tx * 8 + j;
            float v = alpha * acc[i][j];
            if (EPI) {
                float mem = emem[(size_t)z * sMem + (size_t)m * ldc + n];
                C[(size_t)z*sCz + (size_t)m * ldc + n] = mem * (1.f - t) + v;
            } else {
                if (bias) v += bias[n];
                C[(size_t)z*sCz + (size_t)m * ldc + n] = v;
            }
        }
    }
#endif
}

// ---------------- transpose: dst[z][c][r] = src[z][r][c] ----------------
__global__ void transpose_k(const float* __restrict__ src, float* __restrict__ dst,
                            int lds, size_t sSrc, int ldd, size_t sDst)
{
    __shared__ float t[32][33];
    const int z = blockIdx.z;
    const int c0 = blockIdx.x * 32, r0 = blockIdx.y * 32;
    const float* s = src + (size_t)z * sSrc;
    float* d = dst + (size_t)z * sDst;
    const int tx = threadIdx.x, ty = threadIdx.y;
    #pragma unroll
    for (int i = 0; i < 32; i += 8)
        t[ty + i][tx] = s[(size_t)(r0 + ty + i) * lds + c0 + tx];
    __syncthreads();
    #pragma unroll
    for (int i = 0; i < 32; i += 8)
        d[(size_t)(c0 + ty + i) * ldd + r0 + tx] = t[tx][ty + i];
}

// ---------------- fp32 SGEMM (small GEMMs) ----------------
template<bool TA, bool TB, bool EPI>
__global__ __launch_bounds__(256, 2)
void gemm_k(int M, int N, int K, float alpha,
            const float* __restrict__ A, int lda, size_t sA,
            const float* __restrict__ Bp, int ldb, size_t sB,
            const float* __restrict__ bias,
            float* __restrict__ C, int ldc, size_t sC,
            const float* __restrict__ emem, size_t sMem,
            const float* __restrict__ etw, int sTw)
{
    const int bz = blockIdx.z;
    A  += (size_t)bz * sA;
    Bp += (size_t)bz * sB;
    C  += (size_t)bz * sC;
    const int m0 = blockIdx.x * 128;
    const int n0 = blockIdx.y * 128;

    __shared__ float As[8][128];
    __shared__ float Bs[8][128];

    const int tid = threadIdx.x;
    const int tx = tid & 15, ty = tid >> 4;

    float acc[8][8];
    #pragma unroll
    for (int i = 0; i < 8; i++)
        #pragma unroll
        for (int j = 0; j < 8; j++) acc[i][j] = 0.f;

    for (int k0 = 0; k0 < K; k0 += 8) {
        if (!TA) {
            int r = tid >> 1, kq = (tid & 1) * 4;
            int gm = m0 + r;
            float4 v = make_float4(0.f, 0.f, 0.f, 0.f);
            if (gm < M) v = *reinterpret_cast<const float4*>(A + (size_t)gm * lda + (k0 + kq));
            As[kq + 0][r] = v.x; As[kq + 1][r] = v.y;
            As[kq + 2][r] = v.z; As[kq + 3][r] = v.w;
        } else {
            int kr = tid >> 5, mq = (tid & 31) * 4;
            int gm = m0 + mq;
            float4 v = make_float4(0.f, 0.f, 0.f, 0.f);
            if (gm < M) v = *reinterpret_cast<const float4*>(A + (size_t)(k0 + kr) * lda + gm);
            *reinterpret_cast<float4*>(&As[kr][mq]) = v;
        }
        if (!TB) {
            int kr = tid >> 5, nq = (tid & 31) * 4;
            int gn = n0 + nq;
            float4 v = make_float4(0.f, 0.f, 0.f, 0.f);
            if (gn < N) v = *reinterpret_cast<const float4*>(Bp + (size_t)(k0 + kr) * ldb + gn);
            *reinterpret_cast<float4*>(&Bs[kr][nq]) = v;
        } else {
            int r = tid >> 1, kq = (tid & 1) * 4;
            int gn = n0 + r;
            float4 v = make_float4(0.f, 0.f, 0.f, 0.f);
            if (gn < N) v = *reinterpret_cast<const float4*>(Bp + (size_t)gn * ldb + (k0 + kq));
            Bs[kq + 0][r] = v.x; Bs[kq + 1][r] = v.y;
            Bs[kq + 2][r] = v.z; Bs[kq + 3][r] = v.w;
        }
        __syncthreads();
        #pragma unroll
        for (int k = 0; k < 8; k++) {
            float a[8], b[8];
            #pragma unroll
            for (int i = 0; i < 8; i++) a[i] = As[k][ty * 8 + i];
            #pragma unroll
            for (int j = 0; j < 8; j++) b[j] = Bs[k][tx * 8 + j];
            #pragma unroll
            for (int i = 0; i < 8; i++)
                #pragma unroll
                for (int j = 0; j < 8; j++)
                    acc[i][j] = fmaf(a[i], b[j], acc[i][j]);
        }
        __syncthreads();
    }
    #pragma unroll
    for (int i = 0; i < 8; i++) {
        int m = m0 + ty * 8 + i;
        if (m >= M) continue;
        float t = 0.f;
        if (EPI) {
            t = etw[(size_t)bz * sTw + m];
            t = fminf(fmaxf(t, 0.f), 1.f);
        }
        #pragma unroll
        for (int j = 0; j < 8; j++) {
            int n = n0 + tx * 8 + j;
            if (n >= N) continue;
            float v = alpha * acc[i][j];
            if (EPI) {
                float mem = emem[(size_t)bz * sMem + (size_t)m * ldc + n];
                C[(size_t)m * ldc + n] = mem * (1.f - t) + v;
            } else {
                if (bias) v += bias[n];
                C[(size_t)m * ldc + n] = v;
            }
        }
    }
}

// ---------------- small kernels ----------------
__device__ __forceinline__ float sigmoidf_(float x) { return 1.f / (1.f + __expf(-x)); }

__global__ void gate_dot(const float* __restrict__ H, const float* __restrict__ w,
                         const float* __restrict__ b, float* __restrict__ g)
{
    int gt = blockIdx.x * blockDim.x + threadIdx.x;
    int warp = gt >> 5, lane = gt & 31;
    if (warp >= NROW) return;
    const float* h = H + (size_t)warp * RD;
    float s = 0.f;
    for (int j = lane; j < RD; j += 32) s = fmaf(h[j], w[j], s);
    #pragma unroll
    for (int o = 16; o; o >>= 1) s += __shfl_xor_sync(0xffffffffu, s, o);
    if (lane == 0) g[warp] = sigmoidf_(s + b[0]);
}

__global__ void softmax4096(float* __restrict__ S, const float* __restrict__ gate)
{
    int row = blockIdx.x;
    float* p = S + (size_t)row * MEMN;
    __shared__ float buf[MEMN];
    __shared__ float red[256];
    int tid = threadIdx.x;
    float mx = -3.4e38f;
    for (int j = tid; j < MEMN; j += 256) { float v = p[j]; buf[j] = v; mx = fmaxf(mx, v); }
    red[tid] = mx; __syncthreads();
    for (int o = 128; o; o >>= 1) { if (tid < o) red[tid] = fmaxf(red[tid], red[tid + o]); __syncthreads(); }
    mx = red[0]; __syncthreads();
    float s = 0.f;
    for (int j = tid; j < MEMN; j += 256) { float e = __expf(buf[j] - mx); buf[j] = e; s += e; }
    red[tid] = s; __syncthreads();
    for (int o = 128; o; o >>= 1) { if (tid < o) red[tid] += red[tid + o]; __syncthreads(); }
    float inv = (gate ? gate[row] : 1.f) / red[0];
    for (int j = tid; j < MEMN; j += 256) p[j] = buf[j] * inv;
}

__global__ void tw_kernel(const float* __restrict__ S, float* __restrict__ tw)
{
    int m = blockIdx.x * blockDim.x + threadIdx.x;
    int b = blockIdx.y;
    const float* p = S + (size_t)b * A_ * MEMN + m;
    float s = 0.f;
    #pragma unroll 8
    for (int a = 0; a < A_; a++) s += p[(size_t)a * MEMN];
    tw[(size_t)b * MEMN + m] = s;
}

__global__ void gru_kernel(const float* __restrict__ gx, const float* __restrict__ gir,
                           const float* __restrict__ gh, const float* __restrict__ hidden,
                           float* __restrict__ nh)
{
    size_t t = (size_t)blockIdx.x * blockDim.x + threadIdx.x;
    if (t >= (size_t)NROW * RD) return;
    int row = (int)(t >> 9);
    int j   = (int)(t & 511);
    int b   = row >> 8;
    const float* gxr  = gx  + (size_t)b * G3R;
    const float* girr = gir + (size_t)row * G3R;
    const float* ghr  = gh  + (size_t)row * G3R;
    float r = sigmoidf_(gxr[j]        + girr[j]        + ghr[j]);
    float z = sigmoidf_(gxr[RD + j]   + girr[RD + j]   + ghr[RD + j]);
    float n = tanhf(gxr[2*RD + j] + girr[2*RD + j] + r * ghr[2*RD + j]);
    nh[t] = fmaf(z, hidden[t] - n, n);
}

__global__ void qp_kernel(const float* __restrict__ agg_q, const float* __restrict__ proj_w,
                          const float* __restrict__ proj_b, float* __restrict__ qp)
{
    if (blockIdx.x < 4) {
        int j = blockIdx.x * 256 + threadIdx.x;
        float s = 0.f;
        for (int h = 0; h < HIDN; h++) s = fmaf(agg_q[h], proj_w[(size_t)h * IN_ + j], s);
        qp[j] = s;
    } else {
        __shared__ float red[256];
        float s = 0.f;
        for (int h = threadIdx.x; h < HIDN; h += 256) s = fmaf(agg_q[h], proj_b[h], s);
        red[threadIdx.x] = s; __syncthreads();
        for (int o = 128; o; o >>= 1) { if (threadIdx.x < o) red[threadIdx.x] += red[threadIdx.x + o]; __syncthreads(); }
        if (threadIdx.x == 0) qp[IN_] = red[0];
    }
}

__global__ void aggscore_kernel(const float* __restrict__ npu, const float* __restrict__ qp,
                                float* __restrict__ sc)
{
    int gt = blockIdx.x * blockDim.x + threadIdx.x;
    int row = gt >> 5, lane = gt & 31;
    if (row >= NROW) return;
    const float* p = npu + (size_t)row * IN_;
    float s = 0.f;
    for (int j = lane; j < IN_; j += 32) s = fmaf(p[j], qp[j], s);
    #pragma unroll
    for (int o = 16; o; o >>= 1) s += __shfl_xor_sync(0xffffffffu, s, o);
    if (lane == 0) sc[row] = (s + qp[IN_]) * 0.022097086912079612f;
}

__global__ void aggsoftmax_kernel(float* __restrict__ sc)
{
    int b = blockIdx.x, tid = threadIdx.x;
    __shared__ float red[256];
    float v = sc[(size_t)b * A_ + tid];
    red[tid] = v; __syncthreads();
    for (int o = 128; o; o >>= 1) { if (tid < o) red[tid] = fmaxf(red[tid], red[tid + o]); __syncthreads(); }
    float mx = red[0]; __syncthreads();
    float e = __expf(v - mx);
    red[tid] = e; __syncthreads();
    for (int o = 128; o; o >>= 1) { if (tid < o) red[tid] += red[tid + o]; __syncthreads(); }
    sc[(size_t)b * A_ + tid] = e / red[0];
}

__global__ void y_kernel(const float* __restrict__ npu, const float* __restrict__ attn,
                         float* __restrict__ y)
{
    int j = blockIdx.x * blockDim.x + threadIdx.x;
    int b = blockIdx.y;
    const float* base = npu + (size_t)b * A_ * IN_ + j;
    float s = 0.f;
    for (int a = 0; a < A_; a++) s = fmaf(attn[(size_t)b * A_ + a], base[(size_t)a * IN_], s);
    y[(size_t)b * IN_ + j] = s;
}

__global__ void ln_kernel(const float* __restrict__ agg, const float* __restrict__ gamma,
                          const float* __restrict__ beta, float* __restrict__ out)
{
    int b = blockIdx.x, tid = threadIdx.x;
    __shared__ float r1[256], r2[256];
    const float* p = agg + (size_t)b * HIDN;
    float s = 0.f, ss = 0.f;
    for (int h = tid; h < HIDN; h += 256) { float v = p[h]; s += v; ss = fmaf(v, v, ss); }
    r1[tid] = s; r2[tid] = ss; __syncthreads();
    for (int o = 128; o; o >>= 1) {
        if (tid < o) { r1[tid] += r1[tid + o]; r2[tid] += r2[tid + o]; }
        __syncthreads();
    }
    float mu  = r1[0] * (1.f / HIDN);
    float var = r2[0] * (1.f / HIDN) - mu * mu;
    float inv = rsqrtf(var + 1e-5f);
    for (int h = tid; h < HIDN; h += 256)
        out[(size_t)b * HIDN + h] = (p[h] - mu) * inv * gamma[h] + beta[h];
}

// ---------------- host launch ----------------
extern "C" void kernel_launch(void* const* d_in, const int* in_sizes, int n_in,
                              void* d_out, int out_size)
{
    const float* x      = (const float*)d_in[0];
    const float* hidden = (const float*)d_in[1];
    const float* memory = (const float*)d_in[2];
    const float* mmu_w  = (const float*)d_in[3];
    const float* mmu_b  = (const float*)d_in[4];
    const float* w_ih   = (const float*)d_in[5];
    const float* b_ih   = (const float*)d_in[6];
    const float* w_hh   = (const float*)d_in[7];
    const float* b_hh   = (const float*)d_in[8];
    const float* out_w  = (const float*)d_in[9];
    const float* out_b  = (const float*)d_in[10];
    const float* agg_q  = (const float*)d_in[11];
    const float* proj_w = (const float*)d_in[12];
    const float* proj_b = (const float*)d_in[13];
    const float* gamma  = (const float*)d_in[14];
    const float* beta   = (const float*)d_in[15];

    float* out0    = (float*)d_out;
    float* hid_out = out0 + (size_t)B_ * HIDN;
    float* mem_out = hid_out + (size_t)NROW * RD;

    float* scr = nullptr;
    cudaGetSymbolAddress((void**)&scr, g_scr);
    float* qkv  = scr + OFF_QKV;
    float* S    = scr + OFF_S;
    float* St   = scr + OFF_ST;
    float* memT = scr + OFF_MEMT;
    float* Vt   = scr + OFF_VT;
    float* rd   = scr + OFF_RD;
    float* gx   = scr + OFF_GX;
    float* gir  = scr + OFF_GIR;
    float* gh   = scr + OFF_GH;
    float* npu  = scr + OFF_NPU;
    float* gate = scr + OFF_GATE;
    float* tw   = scr + OFF_TW;
    float* qp   = scr + OFF_QP;
    float* asc  = scr + OFF_ASC;
    float* y    = scr + OFF_Y;
    float* agg  = scr + OFF_AGG;

    cudaFuncSetAttribute(tgemm<false>, cudaFuncAttributeMaxDynamicSharedMemorySize, TG_SMEM);
    cudaFuncSetAttribute(tgemm<true>,  cudaFuncAttributeMaxDynamicSharedMemorySize, TG_SMEM);

    const float inv_d = 0.044194173824159216f;  // 1/sqrt(512)
    const dim3 tb(32, 8);

    // memT[z][d][m] = memory[z][m][d]
    transpose_k<<<dim3(RD/32, MEMN/32, B_), tb>>>(memory, memT, RD, (size_t)MEMN*RD, MEMN, (size_t)RD*MEMN);

    // QKV = hidden @ mmu_w[0:1536]^T + mmu_b
    tgemm<false><<<dim3(NROW/128, G3R/128, 1), 256, TG_SMEM>>>(RD, 1.f,
        hidden, RD, 0, mmu_w, RD, 0, mmu_b, qkv, G3R, 0, nullptr, 0, nullptr, 0);
    gate_dot<<<(NROW*32 + 255)/256, 256>>>(hidden, mmu_w + (size_t)3*RD*RD, mmu_b + 3*RD, gate);

    // read scores S = q @ memory^T * inv_d
    tgemm<false><<<dim3(A_/128, MEMN/128, B_), 256, TG_SMEM>>>(RD, inv_d,
        qkv, G3R, (size_t)A_*G3R, memory, RD, (size_t)MEMN*RD, nullptr,
        S, MEMN, (size_t)A_*MEMN, nullptr, 0, nullptr, 0);
    softmax4096<<<NROW, 256>>>(S, nullptr);
    // read_data = S @ memT^T
    tgemm<false><<<dim3(A_/128, RD/128, B_), 256, TG_SMEM>>>(MEMN, 1.f,
        S, MEMN, (size_t)A_*MEMN, memT, MEMN, (size_t)RD*MEMN, nullptr,
        rd, RD, (size_t)A_*RD, nullptr, 0, nullptr, 0);

    // write scores S = k @ memory^T * inv_d
    tgemm<false><<<dim3(A_/128, MEMN/128, B_), 256, TG_SMEM>>>(RD, inv_d,
        qkv + RD, G3R, (size_t)A_*G3R, memory, RD, (size_t)MEMN*RD, nullptr,
        S, MEMN, (size_t)A_*MEMN, nullptr, 0, nullptr, 0);
    softmax4096<<<NROW, 256>>>(S, gate);
    tw_kernel<<<dim3(MEMN/256, B_), 256>>>(S, tw);

    // St[z][m][a] = S[z][a][m];  Vt[z][d][a] = V[z][a][d]
    transpose_k<<<dim3(MEMN/32, A_/32, B_), tb>>>(S, St, MEMN, (size_t)A_*MEMN, A_, (size_t)MEMN*A_);
    transpose_k<<<dim3(RD/32, A_/32, B_), tb>>>(qkv + 2*RD, Vt, G3R, (size_t)A_*G3R, A_, (size_t)RD*A_);

    // new_memory = memory*(1-clip(tw)) + St @ Vt^T
    tgemm<true><<<dim3(MEMN/128, RD/128, B_), 256, TG_SMEM>>>(A_, 1.f,
        St, A_, (size_t)MEMN*A_, Vt, A_, (size_t)RD*A_, nullptr,
        mem_out, RD, (size_t)MEMN*RD, memory, (size_t)MEMN*RD, tw, MEMN);

    // GRU
    gemm_k<false,true,false><<<dim3(1,12,1), 256>>>(B_, G3R, IN_, 1.f,
        x, IN_, 0, w_ih, IN_ + RD, 0, b_ih, gx, G3R, 0, nullptr, 0, nullptr, 0);
    tgemm<false><<<dim3(NROW/128, G3R/128, 1), 256, TG_SMEM>>>(RD, 1.f,
        rd, RD, 0, w_ih + IN_, IN_ + RD, 0, nullptr, gir, G3R, 0, nullptr, 0, nullptr, 0);
    tgemm<false><<<dim3(NROW/128, G3R/128, 1), 256, TG_SMEM>>>(RD, 1.f,
        hidden, RD, 0, w_hh, RD, 0, b_hh, gh, G3R, 0, nullptr, 0, nullptr, 0);
    gru_kernel<<<((size_t)NROW*RD + 255)/256, 256>>>(gx, gir, gh, hidden, hid_out);

    // npu_out = new_regs @ out_w^T + out_b
    tgemm<false><<<dim3(NROW/128, IN_/128, 1), 256, TG_SMEM>>>(RD, 1.f,
        hid_out, RD, 0, out_w, RD, 0, out_b, npu, IN_, 0, nullptr, 0, nullptr, 0);

    // aggregation (proj GEMM eliminated by linearity)
    qp_kernel<<<5, 256>>>(agg_q, proj_w, proj_b, qp);
    aggscore_kernel<<<(NROW*32 + 255)/256, 256>>>(npu, qp, asc);
    aggsoftmax_kernel<<<B_, 256>>>(asc);
    y_kernel<<<dim3(IN_/256, B_), 256>>>(npu, asc, y);
    gemm_k<false,true,false><<<dim3(1,16,1), 256>>>(B_, HIDN, IN_, 1.f,
        y, IN_, 0, proj_w, IN_, 0, proj_b, agg, HIDN, 0, nullptr, 0, nullptr, 0);
    ln_kernel<<<B_, 256>>>(agg, gamma, beta, out0);
}